// round 6
// baseline (speedup 1.0000x reference)
#include <cuda_runtime.h>
#include <cstdint>

// Embedding gather: out[i, :] = table[indices[i], :]
// indices: int32[4194304], table: float32[1000000, 16], out: float32[4194304, 16]
//
// R4 analysis: DRAM traffic stuck at ~405 MB (compulsory 336), achieved BW
// capped at 66% because table misses are random 64 B reads. Fix: a sequential
// prefetch sweep pulls the 64 MB table into L2 (evict_last) as one streaming
// read, then the gather hits L2. Streams (idx reads, out stores) use
// evict-first/streaming ops so they recycle their own L2 lines.

struct __align__(32) f8 { float4 a, b; };

__device__ __forceinline__ uint64_t evict_last_policy() {
    uint64_t policy;
    asm volatile("createpolicy.fractional.L2::evict_last.b64 %0, 1.0;" : "=l"(policy));
    return policy;
}

__device__ __forceinline__ f8 ldg_policy_f8(const f8* p, uint64_t policy) {
    f8 v;
    asm volatile(
        "ld.global.nc.L2::cache_hint.v8.f32 {%0,%1,%2,%3,%4,%5,%6,%7}, [%8], %9;"
        : "=f"(v.a.x), "=f"(v.a.y), "=f"(v.a.z), "=f"(v.a.w),
          "=f"(v.b.x), "=f"(v.b.y), "=f"(v.b.z), "=f"(v.b.w)
        : "l"(p), "l"(policy));
    return v;
}

// ---------------------------------------------------------------------------
// Kernel 1: sequential sweep of the table -> L2 with evict_last priority.
// Loads are asm volatile so they are not dead-code-eliminated; results unused.
// ---------------------------------------------------------------------------
__global__ void __launch_bounds__(256) prefetch_kernel(
    const f8* __restrict__ table8, int total_chunks)
{
    uint64_t policy = evict_last_policy();
    int j = blockIdx.x * blockDim.x + threadIdx.x;
    if (j >= total_chunks) return;
    (void)ldg_policy_f8(&table8[j], policy);
}

// ---------------------------------------------------------------------------
// Kernel 2: the gather. 2 threads per row, 32 B (v8) table load each.
// ---------------------------------------------------------------------------
static constexpr int ROW_HALVES = 2;   // 16 floats = 2 x 32 B halves per row

__global__ void __launch_bounds__(256) gather_kernel(
    const int* __restrict__ indices,
    const f8* __restrict__ table8,
    float4* __restrict__ out4,
    int num_indices)
{
    uint64_t policy = evict_last_policy();

    int j = blockIdx.x * blockDim.x + threadIdx.x;   // 32 B chunk id
    int total = num_indices * ROW_HALVES;
    if (j >= total) return;

    int row = j >> 1;          // output row
    int sub = j & 1;           // which 32 B half of the row

    long long idx = (long long)__ldcs(&indices[row]);
    f8 v = ldg_policy_f8(&table8[idx * ROW_HALVES + sub], policy);

    // streaming stores: evict-first, keep table resident in L2
    __stcs(&out4[j * 2 + 0], v.a);
    __stcs(&out4[j * 2 + 1], v.b);
}

extern "C" void kernel_launch(void* const* d_in, const int* in_sizes, int n_in,
                              void* d_out, int out_size)
{
    // Resolve input order by size: indices = 4,194,304 elems, table = 16,000,000.
    int idx_slot = 0, tab_slot = 1;
    if (n_in >= 2 && in_sizes[0] > in_sizes[1]) { idx_slot = 1; tab_slot = 0; }

    const int* indices = (const int*)d_in[idx_slot];
    const f8*  table8  = (const f8*)d_in[tab_slot];
    float4*    out4    = (float4*)d_out;

    int num_indices  = in_sizes[idx_slot];
    int table_chunks = in_sizes[tab_slot] / 8;       // 32 B chunks: 2,000,000
    int total_chunks = num_indices * ROW_HALVES;     // 8,388,608

    int threads = 256;

    // 1) Stream the table into L2 (evict_last) with perfect coalescing.
    prefetch_kernel<<<(table_chunks + threads - 1) / threads, threads>>>(
        table8, table_chunks);

    // 2) Gather, hitting L2 for the table.
    gather_kernel<<<(total_chunks + threads - 1) / threads, threads>>>(
        indices, table8, out4, num_indices);
}